// round 5
// baseline (speedup 1.0000x reference)
#include <cuda_runtime.h>
#include <cuda_bf16.h>
#include <cuda_fp16.h>
#include <cstdint>
#include <math.h>

// ---------------------------------------------------------------------------
// Problem constants
// ---------------------------------------------------------------------------
#define BATCH 256
#define NC 20
#define NBOX 98
#define KTOP 10
#define CONF_THR 0.1f
#define NMS_THR 0.7f
#define CELLF 64.0f
#define INPUTF 448.0f

#define CONV_CIN 1280
#define CONV_COUT 128
#define M_CONV (BATCH * 49)        // 12544
#define K_FC1 6272
#define N_FC1 4096
#define N_FC2 1470

#define SPLIT1 2
#define SPLIT2 4

// ---------------------------------------------------------------------------
// Device scratch
// ---------------------------------------------------------------------------
__device__ float g_Xs[(size_t)M_CONV * CONV_CIN];
__device__ float g_H1[(size_t)BATCH * K_FC1];
__device__ float g_P1[(size_t)SPLIT1 * BATCH * N_FC1];
__device__ float g_A2[(size_t)BATCH * N_FC1];
__device__ float g_P2[(size_t)SPLIT2 * BATCH * N_FC2];
__device__ float g_F2[(size_t)BATCH * N_FC2];

// ---------------------------------------------------------------------------
// fp16 split helpers
// ---------------------------------------------------------------------------
__device__ __forceinline__ void split_h2(float x, float y, uint32_t& hi, uint32_t& lo) {
    __half hx = __float2half_rn(x);
    __half hy = __float2half_rn(y);
    __half lx = __float2half_rn(x - __half2float(hx));
    __half ly = __float2half_rn(y - __half2float(hy));
    __half2 h = __halves2half2(hx, hy);
    __half2 l = __halves2half2(lx, ly);
    hi = *reinterpret_cast<uint32_t*>(&h);
    lo = *reinterpret_cast<uint32_t*>(&l);
}

__device__ __forceinline__ void mma_f16(float* c, const uint32_t* a, const uint32_t* b) {
    asm volatile(
        "mma.sync.aligned.m16n8k16.row.col.f32.f16.f16.f32 "
        "{%0,%1,%2,%3}, {%4,%5,%6,%7}, {%8,%9}, {%0,%1,%2,%3};"
        : "+f"(c[0]), "+f"(c[1]), "+f"(c[2]), "+f"(c[3])
        : "r"(a[0]), "r"(a[1]), "r"(a[2]), "r"(a[3]), "r"(b[0]), "r"(b[1]));
}

// ---------------------------------------------------------------------------
// Kernel 1: strided slice + transpose  x[b,c,2i,2j] -> Xs[(b*49+p), c]
// ---------------------------------------------------------------------------
__global__ void slice_kernel(const float* __restrict__ x) {
    __shared__ float sm[32 * 98];
    int b = blockIdx.y;
    int c0 = blockIdx.x * 32;
    const float* xb = x + (size_t)b * CONV_CIN * 196;
    for (int idx = threadIdx.x; idx < 32 * 98; idx += blockDim.x) {
        int cc = idx / 98, rem = idx % 98;
        int r = rem / 14, j = rem % 14;
        sm[idx] = xb[(size_t)(c0 + cc) * 196 + r * 28 + j];
    }
    __syncthreads();
    for (int idx = threadIdx.x; idx < 49 * 32; idx += blockDim.x) {
        int p = idx / 32, cc = idx % 32;
        int i = p / 7, j = p % 7;
        g_Xs[((size_t)b * 49 + p) * CONV_CIN + c0 + cc] = sm[cc * 98 + i * 14 + 2 * j];
    }
}

// ---------------------------------------------------------------------------
// mma.sync fp16x3 GEMM.  C[m,n] = sum_k A[m,k]*W[n,k]
//   CFG 0: conv  A=g_Xs -> g_H1 (transposed layout + bias)
//   CFG 1: fc1   A=g_H1 -> g_P1[split]
//   CFG 2: fc2   A=g_A2 -> g_P2[split] (N=1470 guard)
// 128x128 CTA tile, 8 warps (2x4), warp tile 64x32.
// KT=16 floats/chunk = one k16 mma step; hi/lo fp16 split, 3 passes.
// smem: half2-packed, 12 words/row pitch (conflict-free fragment loads).
// ---------------------------------------------------------------------------
#define KT 16
#define PITCHW 12   // 32-bit words per smem row (8 data + 4 pad)

template <int CFG>
__global__ __launch_bounds__(256, 1)
void mma_gemm(const float* __restrict__ W, const float* __restrict__ bias,
              int K, int Ndim, int klen) {
    __shared__ uint32_t sAh[128 * PITCHW];
    __shared__ uint32_t sAl[128 * PITCHW];
    __shared__ uint32_t sBh[128 * PITCHW];
    __shared__ uint32_t sBl[128 * PITCHW];

    int tid = threadIdx.x;
    int warp = tid >> 5;
    int lane = tid & 31;
    int g = lane >> 2;
    int tg = lane & 3;
    int warpM = warp >> 2;          // 0..1
    int warpN = warp & 3;           // 0..3

    int bm = blockIdx.x * 128;
    int bn = blockIdx.y * 128;
    int k0g = blockIdx.z * klen;

    const float* A = (CFG == 0) ? g_Xs : (CFG == 1) ? g_H1 : g_A2;
    const float* Asrc = A + (size_t)bm * K + k0g;
    const float* Wsrc = W + (size_t)bn * K + k0g;

    // staging: 2 float4 of A and 2 of B per thread per chunk
    int rowS[2], qS[2];
#pragma unroll
    for (int v = 0; v < 2; v++) {
        int vid = tid + v * 256;
        rowS[v] = vid >> 2;
        qS[v] = vid & 3;
    }
    bool bok[2];
#pragma unroll
    for (int v = 0; v < 2; v++) bok[v] = (CFG != 2) || (bn + rowS[v] < Ndim);

    float acc[4][4][4];
#pragma unroll
    for (int mt = 0; mt < 4; mt++)
#pragma unroll
        for (int nt = 0; nt < 4; nt++)
#pragma unroll
            for (int c = 0; c < 4; c++) acc[mt][nt][c] = 0.f;

    int nK = klen / KT;
    float4 nA[2], nB[2];

    // prefetch chunk 0
#pragma unroll
    for (int v = 0; v < 2; v++) {
        nA[v] = *reinterpret_cast<const float4*>(Asrc + (size_t)rowS[v] * K + qS[v] * 4);
        nB[v] = bok[v]
            ? *reinterpret_cast<const float4*>(Wsrc + (size_t)rowS[v] * K + qS[v] * 4)
            : make_float4(0.f, 0.f, 0.f, 0.f);
    }

    for (int kt = 0; kt < nK; kt++) {
        // split + store staged chunk into smem (half2-packed)
#pragma unroll
        for (int v = 0; v < 2; v++) {
            int off = rowS[v] * PITCHW + qS[v] * 2;
            uint32_t h0, l0, h1, l1;
            split_h2(nA[v].x, nA[v].y, h0, l0);
            split_h2(nA[v].z, nA[v].w, h1, l1);
            sAh[off] = h0; sAh[off + 1] = h1;
            sAl[off] = l0; sAl[off + 1] = l1;
            split_h2(nB[v].x, nB[v].y, h0, l0);
            split_h2(nB[v].z, nB[v].w, h1, l1);
            sBh[off] = h0; sBh[off + 1] = h1;
            sBl[off] = l0; sBl[off + 1] = l1;
        }
        __syncthreads();

        // prefetch next chunk (LDG latency hides under mma below)
        if (kt + 1 < nK) {
            const float* Ap = Asrc + (kt + 1) * KT;
            const float* Wp = Wsrc + (kt + 1) * KT;
#pragma unroll
            for (int v = 0; v < 2; v++) {
                nA[v] = *reinterpret_cast<const float4*>(Ap + (size_t)rowS[v] * K + qS[v] * 4);
                nB[v] = bok[v]
                    ? *reinterpret_cast<const float4*>(Wp + (size_t)rowS[v] * K + qS[v] * 4)
                    : make_float4(0.f, 0.f, 0.f, 0.f);
            }
        }

        // fragment loads (one k16 step)
        uint32_t ah[4][4], al[4][4], bh[4][2], bl[4][2];
#pragma unroll
        for (int mt = 0; mt < 4; mt++) {
            int base = (warpM * 64 + mt * 16 + g) * PITCHW;
            ah[mt][0] = sAh[base + tg];
            ah[mt][1] = sAh[base + 8 * PITCHW + tg];
            ah[mt][2] = sAh[base + tg + 4];
            ah[mt][3] = sAh[base + 8 * PITCHW + tg + 4];
            al[mt][0] = sAl[base + tg];
            al[mt][1] = sAl[base + 8 * PITCHW + tg];
            al[mt][2] = sAl[base + tg + 4];
            al[mt][3] = sAl[base + 8 * PITCHW + tg + 4];
        }
#pragma unroll
        for (int nt = 0; nt < 4; nt++) {
            int base = (warpN * 32 + nt * 8 + g) * PITCHW;
            bh[nt][0] = sBh[base + tg];
            bh[nt][1] = sBh[base + tg + 4];
            bl[nt][0] = sBl[base + tg];
            bl[nt][1] = sBl[base + tg + 4];
        }

        // 3 split-precision passes
#pragma unroll
        for (int mt = 0; mt < 4; mt++)
#pragma unroll
            for (int nt = 0; nt < 4; nt++) mma_f16(acc[mt][nt], ah[mt], bh[nt]);
#pragma unroll
        for (int mt = 0; mt < 4; mt++)
#pragma unroll
            for (int nt = 0; nt < 4; nt++) mma_f16(acc[mt][nt], ah[mt], bl[nt]);
#pragma unroll
        for (int mt = 0; mt < 4; mt++)
#pragma unroll
            for (int nt = 0; nt < 4; nt++) mma_f16(acc[mt][nt], al[mt], bh[nt]);
        __syncthreads();
    }

    // ---- epilogue ----
    if (CFG == 0) {
        // conv: D[m][n] -> g_H1[bi*6272 + n*49 + p] + bias[n]
#pragma unroll
        for (int mt = 0; mt < 4; mt++) {
#pragma unroll
            for (int nt = 0; nt < 4; nt++) {
                int n = warpN * 32 + nt * 8 + 2 * tg;
                float b0 = __ldg(&bias[n]), b1 = __ldg(&bias[n + 1]);
#pragma unroll
                for (int half = 0; half < 2; half++) {
                    int m = bm + warpM * 64 + mt * 16 + g + half * 8;
                    int bi = m / 49, p = m % 49;
                    float* dst = g_H1 + (size_t)bi * K_FC1 + p;
                    dst[(size_t)n * 49] = acc[mt][nt][half * 2 + 0] + b0;
                    dst[(size_t)(n + 1) * 49] = acc[mt][nt][half * 2 + 1] + b1;
                }
            }
        }
    } else {
        float* C = (CFG == 1) ? (g_P1 + (size_t)blockIdx.z * BATCH * N_FC1)
                              : (g_P2 + (size_t)blockIdx.z * BATCH * N_FC2);
#pragma unroll
        for (int mt = 0; mt < 4; mt++) {
#pragma unroll
            for (int nt = 0; nt < 4; nt++) {
                int n = bn + warpN * 32 + nt * 8 + 2 * tg;
                if (CFG == 2 && n >= Ndim) continue;
#pragma unroll
                for (int half = 0; half < 2; half++) {
                    int m = bm + warpM * 64 + mt * 16 + g + half * 8;
                    float2 v = make_float2(acc[mt][nt][half * 2 + 0], acc[mt][nt][half * 2 + 1]);
                    *reinterpret_cast<float2*>(C + (size_t)m * Ndim + n) = v;
                }
            }
        }
    }
}

// ---------------------------------------------------------------------------
// Split-K reductions with bias + activation
// ---------------------------------------------------------------------------
__global__ void reduce_fc1(const float* __restrict__ bias) {
    int idx = blockIdx.x * blockDim.x + threadIdx.x;
    const int total = BATCH * N_FC1;
    if (idx < total) {
        int n = idx & (N_FC1 - 1);
        float s = bias[n];
#pragma unroll
        for (int sp = 0; sp < SPLIT1; sp++) s += g_P1[(size_t)sp * total + idx];
        g_A2[idx] = (s >= 0.f) ? s : 0.1f * s;
    }
}

__global__ void reduce_fc2(const float* __restrict__ bias) {
    int idx = blockIdx.x * blockDim.x + threadIdx.x;
    const int total = BATCH * N_FC2;
    if (idx < total) {
        int n = idx % N_FC2;
        float s = bias[n];
#pragma unroll
        for (int sp = 0; sp < SPLIT2; sp++) s += g_P2[(size_t)sp * total + idx];
        g_F2[idx] = 1.0f / (1.0f + expf(-s));
    }
}

// ---------------------------------------------------------------------------
// Decode + stable sort + NMS + top-k. One block per image.
// ---------------------------------------------------------------------------
__global__ void nms_kernel(float* __restrict__ out) {
    __shared__ float conf_[NBOX];
    __shared__ float box_[NBOX][4];
    __shared__ int lab_[NBOX];
    __shared__ int order_[NBOX];
    __shared__ float sc_[NBOX];
    __shared__ float sbx_[NBOX][4];
    __shared__ int slb_[NBOX];
    __shared__ float iou_[NBOX * NBOX];
    __shared__ int keep_[NBOX];

    int b = blockIdx.x;
    int tid = threadIdx.x;
    const float* h = g_F2 + (size_t)b * N_FC2;

    if (tid < NBOX) {
        int n = tid;
        int cell = n >> 1;
        int gi = cell / 7, gj = cell % 7;
        float sx = h[n * 4 + 0], sy = h[n * 4 + 1];
        float sw = h[n * 4 + 2], sh = h[n * 4 + 3];
        conf_[n] = h[NBOX * 4 + n];
        const float* cl = h + NBOX * 5 + cell * NC;
        float best = cl[0];
        int bi = 0;
#pragma unroll
        for (int c = 1; c < NC; c++)
            if (cl[c] > best) { best = cl[c]; bi = c; }
        lab_[n] = bi;
        float cx = sx * CELLF + (float)gi * CELLF;
        float cy = sy * CELLF + (float)gj * CELLF;
        float w = sw * INPUTF, hh = sh * INPUTF;
        box_[n][0] = fminf(fmaxf(cx - 0.5f * w, 0.f), INPUTF);
        box_[n][1] = fminf(fmaxf(cy - 0.5f * hh, 0.f), INPUTF);
        box_[n][2] = fminf(fmaxf(cx + 0.5f * w, 0.f), INPUTF);
        box_[n][3] = fminf(fmaxf(cy + 0.5f * hh, 0.f), INPUTF);
    }
    __syncthreads();

    if (tid < NBOX) {
        float c = conf_[tid];
        int r = 0;
        for (int j = 0; j < NBOX; j++)
            r += (conf_[j] > c) || (conf_[j] == c && j < tid);
        order_[r] = tid;
    }
    __syncthreads();
    if (tid < NBOX) {
        int o = order_[tid];
        sc_[tid] = conf_[o];
        slb_[tid] = lab_[o];
        sbx_[tid][0] = box_[o][0]; sbx_[tid][1] = box_[o][1];
        sbx_[tid][2] = box_[o][2]; sbx_[tid][3] = box_[o][3];
    }
    __syncthreads();

    for (int e = tid; e < NBOX * NBOX; e += blockDim.x) {
        int i = e / NBOX, j = e % NBOX;
        float ax1 = sbx_[i][0], ay1 = sbx_[i][1], ax2 = sbx_[i][2], ay2 = sbx_[i][3];
        float bx1 = sbx_[j][0], by1 = sbx_[j][1], bx2 = sbx_[j][2], by2 = sbx_[j][3];
        float areaA = fmaxf(ax2 - ax1, 0.f) * fmaxf(ay2 - ay1, 0.f);
        float areaB = fmaxf(bx2 - bx1, 0.f) * fmaxf(by2 - by1, 0.f);
        float ix1 = fmaxf(ax1, bx1), iy1 = fmaxf(ay1, by1);
        float ix2 = fminf(ax2, bx2), iy2 = fminf(ay2, by2);
        float inter = fmaxf(ix2 - ix1, 0.f) * fmaxf(iy2 - iy1, 0.f);
        float uni = areaA + areaB - inter;
        iou_[e] = (uni > 0.f) ? inter / uni : 0.f;
    }
    if (tid < NBOX) keep_[tid] = (sc_[tid] > CONF_THR) ? 1 : 0;
    __syncthreads();

    for (int i = 0; i < NBOX; i++) {
        if (keep_[i]) {
            for (int j = i + 1 + tid; j < NBOX; j += blockDim.x)
                if (iou_[i * NBOX + j] > NMS_THR) keep_[j] = 0;
        }
        __syncthreads();
    }

    if (tid < NBOX) conf_[tid] = keep_[tid] ? sc_[tid] : -1.0f;
    __syncthreads();
    if (tid < NBOX) {
        float s = conf_[tid];
        int r = 0;
        for (int j = 0; j < NBOX; j++)
            r += (conf_[j] > s) || (conf_[j] == s && j < tid);
        if (r < KTOP) {
            bool valid = s > CONF_THR;
            float* ob = out + ((size_t)b * KTOP + r) * 4;
            ob[0] = valid ? sbx_[tid][0] : 0.f;
            ob[1] = valid ? sbx_[tid][1] : 0.f;
            ob[2] = valid ? sbx_[tid][2] : 0.f;
            ob[3] = valid ? sbx_[tid][3] : 0.f;
            out[BATCH * KTOP * 4 + b * KTOP + r] = valid ? (float)slb_[tid] : 0.f;
            out[BATCH * KTOP * 5 + b * KTOP + r] = valid ? sc_[tid] : 0.f;
        }
    }
}

// ---------------------------------------------------------------------------
// Launch
// ---------------------------------------------------------------------------
extern "C" void kernel_launch(void* const* d_in, const int* in_sizes, int n_in,
                              void* d_out, int out_size) {
    const float* x = (const float*)d_in[0];
    const float* conv_w = (const float*)d_in[1];
    const float* conv_b = (const float*)d_in[2];
    const float* fc1_w = (const float*)d_in[3];
    const float* fc1_b = (const float*)d_in[4];
    const float* fc2_w = (const float*)d_in[5];
    const float* fc2_b = (const float*)d_in[6];
    float* out = (float*)d_out;

    // 1) strided slice + transpose
    slice_kernel<<<dim3(CONV_CIN / 32, BATCH), 256>>>(x);

    // 2) conv GEMM: M=12544, N=128, K=1280 -> 98 CTAs
    mma_gemm<0><<<dim3(M_CONV / 128, 1, 1), 256>>>(conv_w, conv_b,
                                                   CONV_CIN, CONV_COUT, CONV_CIN);

    // 3) fc1: M=256, N=4096, K=6272, split-K=2 -> 128 CTAs
    mma_gemm<1><<<dim3(BATCH / 128, N_FC1 / 128, SPLIT1), 256>>>(fc1_w, nullptr,
                                                                 K_FC1, N_FC1, K_FC1 / SPLIT1);
    reduce_fc1<<<(BATCH * N_FC1 + 255) / 256, 256>>>(fc1_b);

    // 4) fc2: M=256, N=1470 (12 n-tiles), K=4096, split-K=4 -> 96 CTAs
    mma_gemm<2><<<dim3(BATCH / 128, 12, SPLIT2), 256>>>(fc2_w, nullptr,
                                                        N_FC1, N_FC2, N_FC1 / SPLIT2);
    reduce_fc2<<<(BATCH * N_FC2 + 255) / 256, 256>>>(fc2_b);

    // 5) decode + NMS + top-k
    nms_kernel<<<BATCH, 128>>>(out);
}

// round 6
// speedup vs baseline: 1.7793x; 1.7793x over previous
#include <cuda_runtime.h>
#include <cuda_bf16.h>
#include <cuda_fp16.h>
#include <cstdint>
#include <math.h>

// ---------------------------------------------------------------------------
// Problem constants
// ---------------------------------------------------------------------------
#define BATCH 256
#define NC 20
#define NBOX 98
#define KTOP 10
#define CONF_THR 0.1f
#define NMS_THR 0.7f
#define CELLF 64.0f
#define INPUTF 448.0f

#define CONV_CIN 1280
#define CONV_COUT 128
#define M_CONV (BATCH * 49)        // 12544
#define K_FC1 6272
#define N_FC1 4096
#define N_FC2 1470

#define SPLIT1 2
#define SPLIT2 4

// ---------------------------------------------------------------------------
// Device scratch
// ---------------------------------------------------------------------------
__device__ float g_Xs[(size_t)M_CONV * CONV_CIN];
__device__ float g_H1[(size_t)BATCH * K_FC1];
__device__ float g_P1[(size_t)SPLIT1 * BATCH * N_FC1];
__device__ float g_A2[(size_t)BATCH * N_FC1];
__device__ float g_P2[(size_t)SPLIT2 * BATCH * N_FC2];
__device__ float g_F2[(size_t)BATCH * N_FC2];

// ---------------------------------------------------------------------------
// fp16 split helpers
// ---------------------------------------------------------------------------
__device__ __forceinline__ void split_h2(float x, float y, uint32_t& hi, uint32_t& lo) {
    __half hx = __float2half_rn(x);
    __half hy = __float2half_rn(y);
    __half lx = __float2half_rn(x - __half2float(hx));
    __half ly = __float2half_rn(y - __half2float(hy));
    __half2 h = __halves2half2(hx, hy);
    __half2 l = __halves2half2(lx, ly);
    hi = *reinterpret_cast<uint32_t*>(&h);
    lo = *reinterpret_cast<uint32_t*>(&l);
}

__device__ __forceinline__ void mma_f16(float* c, const uint32_t* a, const uint32_t* b) {
    asm volatile(
        "mma.sync.aligned.m16n8k16.row.col.f32.f16.f16.f32 "
        "{%0,%1,%2,%3}, {%4,%5,%6,%7}, {%8,%9}, {%0,%1,%2,%3};"
        : "+f"(c[0]), "+f"(c[1]), "+f"(c[2]), "+f"(c[3])
        : "r"(a[0]), "r"(a[1]), "r"(a[2]), "r"(a[3]), "r"(b[0]), "r"(b[1]));
}

// ---------------------------------------------------------------------------
// Kernel 1: strided slice + transpose  x[b,c,2i,2j] -> Xs[(b*49+p), c]
// ---------------------------------------------------------------------------
__global__ void slice_kernel(const float* __restrict__ x) {
    __shared__ float sm[32 * 98];
    int b = blockIdx.y;
    int c0 = blockIdx.x * 32;
    const float* xb = x + (size_t)b * CONV_CIN * 196;
    for (int idx = threadIdx.x; idx < 32 * 98; idx += blockDim.x) {
        int cc = idx / 98, rem = idx % 98;
        int r = rem / 14, j = rem % 14;
        sm[idx] = xb[(size_t)(c0 + cc) * 196 + r * 28 + j];
    }
    __syncthreads();
    for (int idx = threadIdx.x; idx < 49 * 32; idx += blockDim.x) {
        int p = idx / 32, cc = idx % 32;
        int i = p / 7, j = p % 7;
        g_Xs[((size_t)b * 49 + p) * CONV_CIN + c0 + cc] = sm[cc * 98 + i * 14 + 2 * j];
    }
}

// dummy kernel: shifts the ncu-profiled slot onto the fc1 GEMM
__global__ void dummy_kernel() {}

// ---------------------------------------------------------------------------
// mma.sync fp16x3 GEMM, double-buffered, KT=32, one sync per chunk.
//   CFG 0: conv  A=g_Xs -> g_H1 (transposed layout + bias)
//   CFG 1: fc1   A=g_H1 -> g_P1[split]
//   CFG 2: fc2   A=g_A2 -> g_P2[split] (N=1470 guard)
// 128x128 CTA tile, 8 warps (2x4), warp tile 64x32.
// smem layout per stage: [Ah | Al | Bh | Bl], each 128 rows x PITCHW words.
// ---------------------------------------------------------------------------
#define KT 32
#define PITCHW 20                      // 16 data words (32 halfs) + 4 pad
#define TILE_W (128 * PITCHW)          // words per tile
#define STAGE_W (4 * TILE_W)           // words per stage
#define GEMM_SMEM_BYTES (2 * STAGE_W * 4)

template <int CFG>
__global__ __launch_bounds__(256, 1)
void mma_gemm(const float* __restrict__ W, const float* __restrict__ bias,
              int K, int Ndim, int klen) {
    extern __shared__ uint32_t smem[];

    int tid = threadIdx.x;
    int warp = tid >> 5;
    int lane = tid & 31;
    int g = lane >> 2;
    int tg = lane & 3;
    int warpM = warp >> 2;          // 0..1
    int warpN = warp & 3;           // 0..3

    int bm = blockIdx.x * 128;
    int bn = blockIdx.y * 128;
    int k0g = blockIdx.z * klen;

    const float* A = (CFG == 0) ? g_Xs : (CFG == 1) ? g_H1 : g_A2;
    const float* Asrc = A + (size_t)bm * K + k0g;
    const float* Wsrc = W + (size_t)bn * K + k0g;

    // staging: 4 float4 of A and 4 of B per thread per 32-k chunk
    int rowS[4], qS[4];
#pragma unroll
    for (int v = 0; v < 4; v++) {
        int vid = tid + v * 256;
        rowS[v] = vid >> 3;          // 0..127
        qS[v] = vid & 7;             // float4 index within 32-float row
    }
    bool bok[4];
#pragma unroll
    for (int v = 0; v < 4; v++) bok[v] = (CFG != 2) || (bn + rowS[v] < Ndim);

    float acc[4][4][4];
#pragma unroll
    for (int mt = 0; mt < 4; mt++)
#pragma unroll
        for (int nt = 0; nt < 4; nt++)
#pragma unroll
            for (int c = 0; c < 4; c++) acc[mt][nt][c] = 0.f;

    int nK = klen / KT;
    float4 nA[4], nB[4];

    // --- prologue: load + stage chunk 0 into buffer 0 ---
#pragma unroll
    for (int v = 0; v < 4; v++) {
        nA[v] = *reinterpret_cast<const float4*>(Asrc + (size_t)rowS[v] * K + qS[v] * 4);
        nB[v] = bok[v]
            ? *reinterpret_cast<const float4*>(Wsrc + (size_t)rowS[v] * K + qS[v] * 4)
            : make_float4(0.f, 0.f, 0.f, 0.f);
    }
    {
        uint32_t* st = smem;   // stage 0
#pragma unroll
        for (int v = 0; v < 4; v++) {
            int off = rowS[v] * PITCHW + qS[v] * 2;
            uint32_t h0, l0, h1, l1;
            split_h2(nA[v].x, nA[v].y, h0, l0);
            split_h2(nA[v].z, nA[v].w, h1, l1);
            *reinterpret_cast<uint2*>(&st[off]) = make_uint2(h0, h1);
            *reinterpret_cast<uint2*>(&st[TILE_W + off]) = make_uint2(l0, l1);
            split_h2(nB[v].x, nB[v].y, h0, l0);
            split_h2(nB[v].z, nB[v].w, h1, l1);
            *reinterpret_cast<uint2*>(&st[2 * TILE_W + off]) = make_uint2(h0, h1);
            *reinterpret_cast<uint2*>(&st[3 * TILE_W + off]) = make_uint2(l0, l1);
        }
    }
    __syncthreads();

    for (int kt = 0; kt < nK; kt++) {
        uint32_t* cur = smem + (kt & 1) * STAGE_W;

        // prefetch chunk kt+1 into registers (consumed after the MMAs)
        bool more = (kt + 1 < nK);
        if (more) {
            const float* Ap = Asrc + (kt + 1) * KT;
            const float* Wp = Wsrc + (kt + 1) * KT;
#pragma unroll
            for (int v = 0; v < 4; v++) {
                nA[v] = *reinterpret_cast<const float4*>(Ap + (size_t)rowS[v] * K + qS[v] * 4);
                nB[v] = bok[v]
                    ? *reinterpret_cast<const float4*>(Wp + (size_t)rowS[v] * K + qS[v] * 4)
                    : make_float4(0.f, 0.f, 0.f, 0.f);
            }
        }

        // compute: two k16 steps over this 32-k chunk
        uint32_t* Ah = cur;
        uint32_t* Al = cur + TILE_W;
        uint32_t* Bh = cur + 2 * TILE_W;
        uint32_t* Bl = cur + 3 * TILE_W;
#pragma unroll
        for (int ks = 0; ks < 2; ks++) {
            int ko = ks * 8;
            uint32_t ah[4][4], al[4][4], bh[4][2], bl[4][2];
#pragma unroll
            for (int mt = 0; mt < 4; mt++) {
                int base = (warpM * 64 + mt * 16 + g) * PITCHW + ko;
                ah[mt][0] = Ah[base + tg];
                ah[mt][1] = Ah[base + 8 * PITCHW + tg];
                ah[mt][2] = Ah[base + tg + 4];
                ah[mt][3] = Ah[base + 8 * PITCHW + tg + 4];
                al[mt][0] = Al[base + tg];
                al[mt][1] = Al[base + 8 * PITCHW + tg];
                al[mt][2] = Al[base + tg + 4];
                al[mt][3] = Al[base + 8 * PITCHW + tg + 4];
            }
#pragma unroll
            for (int nt = 0; nt < 4; nt++) {
                int base = (warpN * 32 + nt * 8 + g) * PITCHW + ko;
                bh[nt][0] = Bh[base + tg];
                bh[nt][1] = Bh[base + tg + 4];
                bl[nt][0] = Bl[base + tg];
                bl[nt][1] = Bl[base + tg + 4];
            }
#pragma unroll
            for (int mt = 0; mt < 4; mt++)
#pragma unroll
                for (int nt = 0; nt < 4; nt++) mma_f16(acc[mt][nt], ah[mt], bh[nt]);
#pragma unroll
            for (int mt = 0; mt < 4; mt++)
#pragma unroll
                for (int nt = 0; nt < 4; nt++) mma_f16(acc[mt][nt], ah[mt], bl[nt]);
#pragma unroll
            for (int mt = 0; mt < 4; mt++)
#pragma unroll
                for (int nt = 0; nt < 4; nt++) mma_f16(acc[mt][nt], al[mt], bh[nt]);
        }

        // stage chunk kt+1 into the other buffer (overlaps MMA drain)
        if (more) {
            uint32_t* st = smem + ((kt + 1) & 1) * STAGE_W;
#pragma unroll
            for (int v = 0; v < 4; v++) {
                int off = rowS[v] * PITCHW + qS[v] * 2;
                uint32_t h0, l0, h1, l1;
                split_h2(nA[v].x, nA[v].y, h0, l0);
                split_h2(nA[v].z, nA[v].w, h1, l1);
                *reinterpret_cast<uint2*>(&st[off]) = make_uint2(h0, h1);
                *reinterpret_cast<uint2*>(&st[TILE_W + off]) = make_uint2(l0, l1);
                split_h2(nB[v].x, nB[v].y, h0, l0);
                split_h2(nB[v].z, nB[v].w, h1, l1);
                *reinterpret_cast<uint2*>(&st[2 * TILE_W + off]) = make_uint2(h0, h1);
                *reinterpret_cast<uint2*>(&st[3 * TILE_W + off]) = make_uint2(l0, l1);
            }
        }
        __syncthreads();
    }

    // ---- epilogue ----
    if (CFG == 0) {
        // conv: D[m][n] -> g_H1[bi*6272 + n*49 + p] + bias[n]
#pragma unroll
        for (int mt = 0; mt < 4; mt++) {
#pragma unroll
            for (int nt = 0; nt < 4; nt++) {
                int n = warpN * 32 + nt * 8 + 2 * tg;
                float b0 = __ldg(&bias[n]), b1 = __ldg(&bias[n + 1]);
#pragma unroll
                for (int half = 0; half < 2; half++) {
                    int m = bm + warpM * 64 + mt * 16 + g + half * 8;
                    int bi = m / 49, p = m % 49;
                    float* dst = g_H1 + (size_t)bi * K_FC1 + p;
                    dst[(size_t)n * 49] = acc[mt][nt][half * 2 + 0] + b0;
                    dst[(size_t)(n + 1) * 49] = acc[mt][nt][half * 2 + 1] + b1;
                }
            }
        }
    } else {
        float* C = (CFG == 1) ? (g_P1 + (size_t)blockIdx.z * BATCH * N_FC1)
                              : (g_P2 + (size_t)blockIdx.z * BATCH * N_FC2);
#pragma unroll
        for (int mt = 0; mt < 4; mt++) {
#pragma unroll
            for (int nt = 0; nt < 4; nt++) {
                int n = bn + warpN * 32 + nt * 8 + 2 * tg;
                if (CFG == 2 && n >= Ndim) continue;
#pragma unroll
                for (int half = 0; half < 2; half++) {
                    int m = bm + warpM * 64 + mt * 16 + g + half * 8;
                    float2 v = make_float2(acc[mt][nt][half * 2 + 0], acc[mt][nt][half * 2 + 1]);
                    *reinterpret_cast<float2*>(C + (size_t)m * Ndim + n) = v;
                }
            }
        }
    }
}

// ---------------------------------------------------------------------------
// Split-K reductions with bias + activation
// ---------------------------------------------------------------------------
__global__ void reduce_fc1(const float* __restrict__ bias) {
    int idx = blockIdx.x * blockDim.x + threadIdx.x;
    const int total = BATCH * N_FC1;
    if (idx < total) {
        int n = idx & (N_FC1 - 1);
        float s = bias[n];
#pragma unroll
        for (int sp = 0; sp < SPLIT1; sp++) s += g_P1[(size_t)sp * total + idx];
        g_A2[idx] = (s >= 0.f) ? s : 0.1f * s;
    }
}

__global__ void reduce_fc2(const float* __restrict__ bias) {
    int idx = blockIdx.x * blockDim.x + threadIdx.x;
    const int total = BATCH * N_FC2;
    if (idx < total) {
        int n = idx % N_FC2;
        float s = bias[n];
#pragma unroll
        for (int sp = 0; sp < SPLIT2; sp++) s += g_P2[(size_t)sp * total + idx];
        g_F2[idx] = 1.0f / (1.0f + expf(-s));
    }
}

// ---------------------------------------------------------------------------
// Decode + stable sort + NMS + top-k. One block per image.
// ---------------------------------------------------------------------------
__global__ void nms_kernel(float* __restrict__ out) {
    __shared__ float conf_[NBOX];
    __shared__ float box_[NBOX][4];
    __shared__ int lab_[NBOX];
    __shared__ int order_[NBOX];
    __shared__ float sc_[NBOX];
    __shared__ float sbx_[NBOX][4];
    __shared__ int slb_[NBOX];
    __shared__ float iou_[NBOX * NBOX];
    __shared__ int keep_[NBOX];

    int b = blockIdx.x;
    int tid = threadIdx.x;
    const float* h = g_F2 + (size_t)b * N_FC2;

    if (tid < NBOX) {
        int n = tid;
        int cell = n >> 1;
        int gi = cell / 7, gj = cell % 7;
        float sx = h[n * 4 + 0], sy = h[n * 4 + 1];
        float sw = h[n * 4 + 2], sh = h[n * 4 + 3];
        conf_[n] = h[NBOX * 4 + n];
        const float* cl = h + NBOX * 5 + cell * NC;
        float best = cl[0];
        int bi = 0;
#pragma unroll
        for (int c = 1; c < NC; c++)
            if (cl[c] > best) { best = cl[c]; bi = c; }
        lab_[n] = bi;
        float cx = sx * CELLF + (float)gi * CELLF;
        float cy = sy * CELLF + (float)gj * CELLF;
        float w = sw * INPUTF, hh = sh * INPUTF;
        box_[n][0] = fminf(fmaxf(cx - 0.5f * w, 0.f), INPUTF);
        box_[n][1] = fminf(fmaxf(cy - 0.5f * hh, 0.f), INPUTF);
        box_[n][2] = fminf(fmaxf(cx + 0.5f * w, 0.f), INPUTF);
        box_[n][3] = fminf(fmaxf(cy + 0.5f * hh, 0.f), INPUTF);
    }
    __syncthreads();

    if (tid < NBOX) {
        float c = conf_[tid];
        int r = 0;
        for (int j = 0; j < NBOX; j++)
            r += (conf_[j] > c) || (conf_[j] == c && j < tid);
        order_[r] = tid;
    }
    __syncthreads();
    if (tid < NBOX) {
        int o = order_[tid];
        sc_[tid] = conf_[o];
        slb_[tid] = lab_[o];
        sbx_[tid][0] = box_[o][0]; sbx_[tid][1] = box_[o][1];
        sbx_[tid][2] = box_[o][2]; sbx_[tid][3] = box_[o][3];
    }
    __syncthreads();

    for (int e = tid; e < NBOX * NBOX; e += blockDim.x) {
        int i = e / NBOX, j = e % NBOX;
        float ax1 = sbx_[i][0], ay1 = sbx_[i][1], ax2 = sbx_[i][2], ay2 = sbx_[i][3];
        float bx1 = sbx_[j][0], by1 = sbx_[j][1], bx2 = sbx_[j][2], by2 = sbx_[j][3];
        float areaA = fmaxf(ax2 - ax1, 0.f) * fmaxf(ay2 - ay1, 0.f);
        float areaB = fmaxf(bx2 - bx1, 0.f) * fmaxf(by2 - by1, 0.f);
        float ix1 = fmaxf(ax1, bx1), iy1 = fmaxf(ay1, by1);
        float ix2 = fminf(ax2, bx2), iy2 = fminf(ay2, by2);
        float inter = fmaxf(ix2 - ix1, 0.f) * fmaxf(iy2 - iy1, 0.f);
        float uni = areaA + areaB - inter;
        iou_[e] = (uni > 0.f) ? inter / uni : 0.f;
    }
    if (tid < NBOX) keep_[tid] = (sc_[tid] > CONF_THR) ? 1 : 0;
    __syncthreads();

    for (int i = 0; i < NBOX; i++) {
        if (keep_[i]) {
            for (int j = i + 1 + tid; j < NBOX; j += blockDim.x)
                if (iou_[i * NBOX + j] > NMS_THR) keep_[j] = 0;
        }
        __syncthreads();
    }

    if (tid < NBOX) conf_[tid] = keep_[tid] ? sc_[tid] : -1.0f;
    __syncthreads();
    if (tid < NBOX) {
        float s = conf_[tid];
        int r = 0;
        for (int j = 0; j < NBOX; j++)
            r += (conf_[j] > s) || (conf_[j] == s && j < tid);
        if (r < KTOP) {
            bool valid = s > CONF_THR;
            float* ob = out + ((size_t)b * KTOP + r) * 4;
            ob[0] = valid ? sbx_[tid][0] : 0.f;
            ob[1] = valid ? sbx_[tid][1] : 0.f;
            ob[2] = valid ? sbx_[tid][2] : 0.f;
            ob[3] = valid ? sbx_[tid][3] : 0.f;
            out[BATCH * KTOP * 4 + b * KTOP + r] = valid ? (float)slb_[tid] : 0.f;
            out[BATCH * KTOP * 5 + b * KTOP + r] = valid ? sc_[tid] : 0.f;
        }
    }
}

// ---------------------------------------------------------------------------
// Launch
// ---------------------------------------------------------------------------
extern "C" void kernel_launch(void* const* d_in, const int* in_sizes, int n_in,
                              void* d_out, int out_size) {
    const float* x = (const float*)d_in[0];
    const float* conv_w = (const float*)d_in[1];
    const float* conv_b = (const float*)d_in[2];
    const float* fc1_w = (const float*)d_in[3];
    const float* fc1_b = (const float*)d_in[4];
    const float* fc2_w = (const float*)d_in[5];
    const float* fc2_b = (const float*)d_in[6];
    float* out = (float*)d_out;

    cudaFuncSetAttribute(mma_gemm<0>, cudaFuncAttributeMaxDynamicSharedMemorySize, GEMM_SMEM_BYTES);
    cudaFuncSetAttribute(mma_gemm<1>, cudaFuncAttributeMaxDynamicSharedMemorySize, GEMM_SMEM_BYTES);
    cudaFuncSetAttribute(mma_gemm<2>, cudaFuncAttributeMaxDynamicSharedMemorySize, GEMM_SMEM_BYTES);

    // 1) strided slice + transpose
    slice_kernel<<<dim3(CONV_CIN / 32, BATCH), 256>>>(x);

    // 2) conv GEMM: M=12544, N=128, K=1280 -> 98 CTAs
    mma_gemm<0><<<dim3(M_CONV / 128, 1, 1), 256, GEMM_SMEM_BYTES>>>(
        conv_w, conv_b, CONV_CIN, CONV_COUT, CONV_CIN);

    // 3) dummy shifts fc1 GEMM into ncu's profiled slot (launch #4)
    dummy_kernel<<<1, 32>>>();

    // 4) fc1: M=256, N=4096, K=6272, split-K=2 -> 128 CTAs
    mma_gemm<1><<<dim3(BATCH / 128, N_FC1 / 128, SPLIT1), 256, GEMM_SMEM_BYTES>>>(
        fc1_w, nullptr, K_FC1, N_FC1, K_FC1 / SPLIT1);
    reduce_fc1<<<(BATCH * N_FC1 + 255) / 256, 256>>>(fc1_b);

    // 5) fc2: M=256, N=1470 (12 n-tiles), K=4096, split-K=4 -> 96 CTAs
    mma_gemm<2><<<dim3(BATCH / 128, 12, SPLIT2), 256, GEMM_SMEM_BYTES>>>(
        fc2_w, nullptr, N_FC1, N_FC2, N_FC1 / SPLIT2);
    reduce_fc2<<<(BATCH * N_FC2 + 255) / 256, 256>>>(fc2_b);

    // 6) decode + NMS + top-k
    nms_kernel<<<BATCH, 128>>>(out);
}

// round 8
// speedup vs baseline: 1.8365x; 1.0321x over previous
#include <cuda_runtime.h>
#include <cuda_bf16.h>
#include <cuda_fp16.h>
#include <cstdint>
#include <math.h>

// ---------------------------------------------------------------------------
// Problem constants
// ---------------------------------------------------------------------------
#define BATCH 256
#define NC 20
#define NBOX 98
#define KTOP 10
#define CONF_THR 0.1f
#define NMS_THR 0.7f
#define CELLF 64.0f
#define INPUTF 448.0f

#define CONV_CIN 1280
#define CONV_COUT 128
#define M_CONV (BATCH * 49)        // 12544
#define K_FC1 6272
#define N_FC1 4096
#define N_FC2 1470

#define SPLIT1 2
#define SPLIT2 4

// ---------------------------------------------------------------------------
// Device scratch
// ---------------------------------------------------------------------------
__device__ float g_Xs[(size_t)M_CONV * CONV_CIN];
__device__ float g_H1[(size_t)BATCH * K_FC1];
__device__ float g_P1[(size_t)SPLIT1 * BATCH * N_FC1];
__device__ float g_A2[(size_t)BATCH * N_FC1];
__device__ float g_P2[(size_t)SPLIT2 * BATCH * N_FC2];
__device__ float g_F2[(size_t)BATCH * N_FC2];

// ---------------------------------------------------------------------------
// helpers
// ---------------------------------------------------------------------------
__device__ __forceinline__ uint32_t smem_u32(const void* p) {
    uint32_t a;
    asm("{ .reg .u64 t; cvta.to.shared.u64 t, %1; cvt.u32.u64 %0, t; }" : "=r"(a) : "l"(p));
    return a;
}

__device__ __forceinline__ void split_h2(float x, float y, uint32_t& hi, uint32_t& lo) {
    __half hx = __float2half_rn(x);
    __half hy = __float2half_rn(y);
    __half lx = __float2half_rn(x - __half2float(hx));
    __half ly = __float2half_rn(y - __half2float(hy));
    __half2 h = __halves2half2(hx, hy);
    __half2 l = __halves2half2(lx, ly);
    hi = *reinterpret_cast<uint32_t*>(&h);
    lo = *reinterpret_cast<uint32_t*>(&l);
}

__device__ __forceinline__ void mma_f16(float* c, const uint32_t* a, const uint32_t* b) {
    asm volatile(
        "mma.sync.aligned.m16n8k16.row.col.f32.f16.f16.f32 "
        "{%0,%1,%2,%3}, {%4,%5,%6,%7}, {%8,%9}, {%0,%1,%2,%3};"
        : "+f"(c[0]), "+f"(c[1]), "+f"(c[2]), "+f"(c[3])
        : "r"(a[0]), "r"(a[1]), "r"(a[2]), "r"(a[3]), "r"(b[0]), "r"(b[1]));
}

__device__ __forceinline__ void ldsm_x4(uint32_t& r0, uint32_t& r1, uint32_t& r2, uint32_t& r3,
                                        uint32_t addr) {
    asm volatile("ldmatrix.sync.aligned.m8n8.x4.shared.b16 {%0,%1,%2,%3}, [%4];"
                 : "=r"(r0), "=r"(r1), "=r"(r2), "=r"(r3) : "r"(addr));
}

// ---------------------------------------------------------------------------
// Kernel 1: strided slice + transpose  x[b,c,2i,2j] -> Xs[(b*49+p), c]
// ---------------------------------------------------------------------------
__global__ void slice_kernel(const float* __restrict__ x) {
    __shared__ float sm[32 * 98];
    int b = blockIdx.y;
    int c0 = blockIdx.x * 32;
    const float* xb = x + (size_t)b * CONV_CIN * 196;
    for (int idx = threadIdx.x; idx < 32 * 98; idx += blockDim.x) {
        int cc = idx / 98, rem = idx % 98;
        int r = rem / 14, j = rem % 14;
        sm[idx] = xb[(size_t)(c0 + cc) * 196 + r * 28 + j];
    }
    __syncthreads();
    for (int idx = threadIdx.x; idx < 49 * 32; idx += blockDim.x) {
        int p = idx / 32, cc = idx % 32;
        int i = p / 7, j = p % 7;
        g_Xs[((size_t)b * 49 + p) * CONV_CIN + c0 + cc] = sm[cc * 98 + i * 14 + 2 * j];
    }
}

// dummy kernel: keeps the fc1 GEMM in ncu's profiled slot (launch #4)
__global__ void dummy_kernel() {}

// ---------------------------------------------------------------------------
// mma.sync fp16x3 GEMM, double-buffered, KT=32, ldmatrix fragment loads.
//   CFG 0: conv  A=g_Xs -> g_H1 (transposed layout + bias)
//   CFG 1: fc1   A=g_H1 -> g_P1[split]
//   CFG 2: fc2   A=g_A2 -> g_P2[split] (N=1470 guard)
// 128x128 CTA tile, 8 warps (2x4), warp tile 64x32.
// smem per stage: [Ah | Al | Bh | Bl], each 128 rows x PITCHW words (80B pitch).
// ---------------------------------------------------------------------------
#define KT 32
#define PITCHW 20                       // 16 data words (32 halfs) + 4 pad
#define TILE_W (128 * PITCHW)           // words per tile
#define STAGE_W (4 * TILE_W)            // words per stage
#define TILE_B (TILE_W * 4)             // bytes per tile
#define STAGE_B (STAGE_W * 4)
#define GEMM_SMEM_BYTES (2 * STAGE_B)

template <int CFG>
__global__ __launch_bounds__(256, 1)
void mma_gemm(const float* __restrict__ W, const float* __restrict__ bias,
              int K, int Ndim, int klen) {
    extern __shared__ uint32_t smem[];
    uint32_t sbase = smem_u32(smem);

    int tid = threadIdx.x;
    int warp = tid >> 5;
    int lane = tid & 31;
    int g = lane >> 2;
    int tg = lane & 3;
    int warpM = warp >> 2;          // 0..1
    int warpN = warp & 3;           // 0..3

    int bm = blockIdx.x * 128;
    int bn = blockIdx.y * 128;
    int k0g = blockIdx.z * klen;

    const float* A = (CFG == 0) ? g_Xs : (CFG == 1) ? g_H1 : g_A2;
    const float* Asrc = A + (size_t)bm * K + k0g;
    const float* Wsrc = W + (size_t)bn * K + k0g;

    // ldmatrix lane address components (bytes within a tile)
    int quad = lane >> 3, l8 = lane & 7;
    // A: row = warpM*64 + mt*16 + (quad&1)*8 + l8 ; k-halfword group = (quad>>1)
    uint32_t aOff = ((uint32_t)(warpM * 64 + (quad & 1) * 8 + l8) * PITCHW + (quad >> 1) * 4) * 4;
    // B: row = warpN*32 + ntp*16 + (quad>>1)*8 + l8 ; k group = (quad&1)
    uint32_t bOff = ((uint32_t)(warpN * 32 + (quad >> 1) * 8 + l8) * PITCHW + (quad & 1) * 4) * 4;

    // staging: 4 float4 of A and 4 of B per thread per 32-k chunk
    int rowS[4], qS[4];
#pragma unroll
    for (int v = 0; v < 4; v++) {
        int vid = tid + v * 256;
        rowS[v] = vid >> 3;          // 0..127
        qS[v] = vid & 7;             // float4 index within 32-float row
    }
    bool bok[4];
#pragma unroll
    for (int v = 0; v < 4; v++) bok[v] = (CFG != 2) || (bn + rowS[v] < Ndim);

    float acc[4][4][4];
#pragma unroll
    for (int mt = 0; mt < 4; mt++)
#pragma unroll
        for (int nt = 0; nt < 4; nt++)
#pragma unroll
            for (int c = 0; c < 4; c++) acc[mt][nt][c] = 0.f;

    int nK = klen / KT;
    float4 nA[4], nB[4];

    // --- prologue: load + stage chunk 0 into buffer 0 ---
#pragma unroll
    for (int v = 0; v < 4; v++) {
        nA[v] = *reinterpret_cast<const float4*>(Asrc + (size_t)rowS[v] * K + qS[v] * 4);
        nB[v] = bok[v]
            ? *reinterpret_cast<const float4*>(Wsrc + (size_t)rowS[v] * K + qS[v] * 4)
            : make_float4(0.f, 0.f, 0.f, 0.f);
    }
    {
        uint32_t* st = smem;
#pragma unroll
        for (int v = 0; v < 4; v++) {
            int off = rowS[v] * PITCHW + qS[v] * 2;
            uint32_t h0, l0, h1, l1;
            split_h2(nA[v].x, nA[v].y, h0, l0);
            split_h2(nA[v].z, nA[v].w, h1, l1);
            *reinterpret_cast<uint2*>(&st[off]) = make_uint2(h0, h1);
            *reinterpret_cast<uint2*>(&st[TILE_W + off]) = make_uint2(l0, l1);
            split_h2(nB[v].x, nB[v].y, h0, l0);
            split_h2(nB[v].z, nB[v].w, h1, l1);
            *reinterpret_cast<uint2*>(&st[2 * TILE_W + off]) = make_uint2(h0, h1);
            *reinterpret_cast<uint2*>(&st[3 * TILE_W + off]) = make_uint2(l0, l1);
        }
    }
    __syncthreads();

    for (int kt = 0; kt < nK; kt++) {
        uint32_t sb = sbase + (kt & 1) * STAGE_B;

        // prefetch chunk kt+1 into registers (consumed after the MMAs)
        bool more = (kt + 1 < nK);
        if (more) {
            const float* Ap = Asrc + (kt + 1) * KT;
            const float* Wp = Wsrc + (kt + 1) * KT;
#pragma unroll
            for (int v = 0; v < 4; v++) {
                nA[v] = *reinterpret_cast<const float4*>(Ap + (size_t)rowS[v] * K + qS[v] * 4);
                nB[v] = bok[v]
                    ? *reinterpret_cast<const float4*>(Wp + (size_t)rowS[v] * K + qS[v] * 4)
                    : make_float4(0.f, 0.f, 0.f, 0.f);
            }
        }

        // compute: two k16 steps over this 32-k chunk, fragments via ldmatrix
#pragma unroll
        for (int ks = 0; ks < 2; ks++) {
            uint32_t ko = ks * 32;   // 8 words = 32 bytes
            uint32_t ah[4][4], al[4][4], bh[4][2], bl[4][2];
#pragma unroll
            for (int mt = 0; mt < 4; mt++) {
                uint32_t adr = sb + aOff + (uint32_t)mt * (16 * PITCHW * 4) + ko;
                ldsm_x4(ah[mt][0], ah[mt][1], ah[mt][2], ah[mt][3], adr);
                ldsm_x4(al[mt][0], al[mt][1], al[mt][2], al[mt][3], adr + TILE_B);
            }
#pragma unroll
            for (int ntp = 0; ntp < 2; ntp++) {
                uint32_t adr = sb + 2 * TILE_B + bOff + (uint32_t)ntp * (16 * PITCHW * 4) + ko;
                ldsm_x4(bh[2 * ntp][0], bh[2 * ntp][1], bh[2 * ntp + 1][0], bh[2 * ntp + 1][1], adr);
                ldsm_x4(bl[2 * ntp][0], bl[2 * ntp][1], bl[2 * ntp + 1][0], bl[2 * ntp + 1][1],
                        adr + TILE_B);
            }
#pragma unroll
            for (int mt = 0; mt < 4; mt++)
#pragma unroll
                for (int nt = 0; nt < 4; nt++) mma_f16(acc[mt][nt], ah[mt], bh[nt]);
#pragma unroll
            for (int mt = 0; mt < 4; mt++)
#pragma unroll
                for (int nt = 0; nt < 4; nt++) mma_f16(acc[mt][nt], ah[mt], bl[nt]);
#pragma unroll
            for (int mt = 0; mt < 4; mt++)
#pragma unroll
                for (int nt = 0; nt < 4; nt++) mma_f16(acc[mt][nt], al[mt], bh[nt]);
        }

        // stage chunk kt+1 into the other buffer (overlaps MMA drain)
        if (more) {
            uint32_t* st = smem + ((kt + 1) & 1) * STAGE_W;
#pragma unroll
            for (int v = 0; v < 4; v++) {
                int off = rowS[v] * PITCHW + qS[v] * 2;
                uint32_t h0, l0, h1, l1;
                split_h2(nA[v].x, nA[v].y, h0, l0);
                split_h2(nA[v].z, nA[v].w, h1, l1);
                *reinterpret_cast<uint2*>(&st[off]) = make_uint2(h0, h1);
                *reinterpret_cast<uint2*>(&st[TILE_W + off]) = make_uint2(l0, l1);
                split_h2(nB[v].x, nB[v].y, h0, l0);
                split_h2(nB[v].z, nB[v].w, h1, l1);
                *reinterpret_cast<uint2*>(&st[2 * TILE_W + off]) = make_uint2(h0, h1);
                *reinterpret_cast<uint2*>(&st[3 * TILE_W + off]) = make_uint2(l0, l1);
            }
        }
        __syncthreads();
    }

    // ---- epilogue ----
    if (CFG == 0) {
        // conv: D[m][n] -> g_H1[bi*6272 + n*49 + p] + bias[n]
#pragma unroll
        for (int mt = 0; mt < 4; mt++) {
#pragma unroll
            for (int nt = 0; nt < 4; nt++) {
                int n = warpN * 32 + nt * 8 + 2 * tg;
                float b0 = __ldg(&bias[n]), b1 = __ldg(&bias[n + 1]);
#pragma unroll
                for (int half = 0; half < 2; half++) {
                    int m = bm + warpM * 64 + mt * 16 + g + half * 8;
                    int bi = m / 49, p = m % 49;
                    float* dst = g_H1 + (size_t)bi * K_FC1 + p;
                    dst[(size_t)n * 49] = acc[mt][nt][half * 2 + 0] + b0;
                    dst[(size_t)(n + 1) * 49] = acc[mt][nt][half * 2 + 1] + b1;
                }
            }
        }
    } else {
        float* C = (CFG == 1) ? (g_P1 + (size_t)blockIdx.z * BATCH * N_FC1)
                              : (g_P2 + (size_t)blockIdx.z * BATCH * N_FC2);
#pragma unroll
        for (int mt = 0; mt < 4; mt++) {
#pragma unroll
            for (int nt = 0; nt < 4; nt++) {
                int n = bn + warpN * 32 + nt * 8 + 2 * tg;
                if (CFG == 2 && n >= Ndim) continue;
#pragma unroll
                for (int half = 0; half < 2; half++) {
                    int m = bm + warpM * 64 + mt * 16 + g + half * 8;
                    float2 v = make_float2(acc[mt][nt][half * 2 + 0], acc[mt][nt][half * 2 + 1]);
                    *reinterpret_cast<float2*>(C + (size_t)m * Ndim + n) = v;
                }
            }
        }
    }
}

// ---------------------------------------------------------------------------
// Split-K reductions with bias + activation
// ---------------------------------------------------------------------------
__global__ void reduce_fc1(const float* __restrict__ bias) {
    int idx = blockIdx.x * blockDim.x + threadIdx.x;
    const int total = BATCH * N_FC1;
    if (idx < total) {
        int n = idx & (N_FC1 - 1);
        float s = bias[n];
#pragma unroll
        for (int sp = 0; sp < SPLIT1; sp++) s += g_P1[(size_t)sp * total + idx];
        g_A2[idx] = (s >= 0.f) ? s : 0.1f * s;
    }
}

__global__ void reduce_fc2(const float* __restrict__ bias) {
    int idx = blockIdx.x * blockDim.x + threadIdx.x;
    const int total = BATCH * N_FC2;
    if (idx < total) {
        int n = idx % N_FC2;
        float s = bias[n];
#pragma unroll
        for (int sp = 0; sp < SPLIT2; sp++) s += g_P2[(size_t)sp * total + idx];
        g_F2[idx] = 1.0f / (1.0f + expf(-s));
    }
}

// ---------------------------------------------------------------------------
// Decode + stable sort + NMS + top-k. One block per image.
// ---------------------------------------------------------------------------
__global__ void nms_kernel(float* __restrict__ out) {
    __shared__ float conf_[NBOX];
    __shared__ float box_[NBOX][4];
    __shared__ int lab_[NBOX];
    __shared__ int order_[NBOX];
    __shared__ float sc_[NBOX];
    __shared__ float sbx_[NBOX][4];
    __shared__ int slb_[NBOX];
    __shared__ float iou_[NBOX * NBOX];
    __shared__ int keep_[NBOX];

    int b = blockIdx.x;
    int tid = threadIdx.x;
    const float* h = g_F2 + (size_t)b * N_FC2;

    if (tid < NBOX) {
        int n = tid;
        int cell = n >> 1;
        int gi = cell / 7, gj = cell % 7;
        float sx = h[n * 4 + 0], sy = h[n * 4 + 1];
        float sw = h[n * 4 + 2], sh = h[n * 4 + 3];
        conf_[n] = h[NBOX * 4 + n];
        const float* cl = h + NBOX * 5 + cell * NC;
        float best = cl[0];
        int bi = 0;
#pragma unroll
        for (int c = 1; c < NC; c++)
            if (cl[c] > best) { best = cl[c]; bi = c; }
        lab_[n] = bi;
        float cx = sx * CELLF + (float)gi * CELLF;
        float cy = sy * CELLF + (float)gj * CELLF;
        float w = sw * INPUTF, hh = sh * INPUTF;
        box_[n][0] = fminf(fmaxf(cx - 0.5f * w, 0.f), INPUTF);
        box_[n][1] = fminf(fmaxf(cy - 0.5f * hh, 0.f), INPUTF);
        box_[n][2] = fminf(fmaxf(cx + 0.5f * w, 0.f), INPUTF);
        box_[n][3] = fminf(fmaxf(cy + 0.5f * hh, 0.f), INPUTF);
    }
    __syncthreads();

    if (tid < NBOX) {
        float c = conf_[tid];
        int r = 0;
        for (int j = 0; j < NBOX; j++)
            r += (conf_[j] > c) || (conf_[j] == c && j < tid);
        order_[r] = tid;
    }
    __syncthreads();
    if (tid < NBOX) {
        int o = order_[tid];
        sc_[tid] = conf_[o];
        slb_[tid] = lab_[o];
        sbx_[tid][0] = box_[o][0]; sbx_[tid][1] = box_[o][1];
        sbx_[tid][2] = box_[o][2]; sbx_[tid][3] = box_[o][3];
    }
    __syncthreads();

    for (int e = tid; e < NBOX * NBOX; e += blockDim.x) {
        int i = e / NBOX, j = e % NBOX;
        float ax1 = sbx_[i][0], ay1 = sbx_[i][1], ax2 = sbx_[i][2], ay2 = sbx_[i][3];
        float bx1 = sbx_[j][0], by1 = sbx_[j][1], bx2 = sbx_[j][2], by2 = sbx_[j][3];
        float areaA = fmaxf(ax2 - ax1, 0.f) * fmaxf(ay2 - ay1, 0.f);
        float areaB = fmaxf(bx2 - bx1, 0.f) * fmaxf(by2 - by1, 0.f);
        float ix1 = fmaxf(ax1, bx1), iy1 = fmaxf(ay1, by1);
        float ix2 = fminf(ax2, bx2), iy2 = fminf(ay2, by2);
        float inter = fmaxf(ix2 - ix1, 0.f) * fmaxf(iy2 - iy1, 0.f);
        float uni = areaA + areaB - inter;
        iou_[e] = (uni > 0.f) ? inter / uni : 0.f;
    }
    if (tid < NBOX) keep_[tid] = (sc_[tid] > CONF_THR) ? 1 : 0;
    __syncthreads();

    for (int i = 0; i < NBOX; i++) {
        if (keep_[i]) {
            for (int j = i + 1 + tid; j < NBOX; j += blockDim.x)
                if (iou_[i * NBOX + j] > NMS_THR) keep_[j] = 0;
        }
        __syncthreads();
    }

    if (tid < NBOX) conf_[tid] = keep_[tid] ? sc_[tid] : -1.0f;
    __syncthreads();
    if (tid < NBOX) {
        float s = conf_[tid];
        int r = 0;
        for (int j = 0; j < NBOX; j++)
            r += (conf_[j] > s) || (conf_[j] == s && j < tid);
        if (r < KTOP) {
            bool valid = s > CONF_THR;
            float* ob = out + ((size_t)b * KTOP + r) * 4;
            ob[0] = valid ? sbx_[tid][0] : 0.f;
            ob[1] = valid ? sbx_[tid][1] : 0.f;
            ob[2] = valid ? sbx_[tid][2] : 0.f;
            ob[3] = valid ? sbx_[tid][3] : 0.f;
            out[BATCH * KTOP * 4 + b * KTOP + r] = valid ? (float)slb_[tid] : 0.f;
            out[BATCH * KTOP * 5 + b * KTOP + r] = valid ? sc_[tid] : 0.f;
        }
    }
}

// ---------------------------------------------------------------------------
// Launch
// ---------------------------------------------------------------------------
extern "C" void kernel_launch(void* const* d_in, const int* in_sizes, int n_in,
                              void* d_out, int out_size) {
    const float* x = (const float*)d_in[0];
    const float* conv_w = (const float*)d_in[1];
    const float* conv_b = (const float*)d_in[2];
    const float* fc1_w = (const float*)d_in[3];
    const float* fc1_b = (const float*)d_in[4];
    const float* fc2_w = (const float*)d_in[5];
    const float* fc2_b = (const float*)d_in[6];
    float* out = (float*)d_out;

    cudaFuncSetAttribute(mma_gemm<0>, cudaFuncAttributeMaxDynamicSharedMemorySize, GEMM_SMEM_BYTES);
    cudaFuncSetAttribute(mma_gemm<1>, cudaFuncAttributeMaxDynamicSharedMemorySize, GEMM_SMEM_BYTES);
    cudaFuncSetAttribute(mma_gemm<2>, cudaFuncAttributeMaxDynamicSharedMemorySize, GEMM_SMEM_BYTES);

    // 1) strided slice + transpose
    slice_kernel<<<dim3(CONV_CIN / 32, BATCH), 256>>>(x);

    // 2) conv GEMM: M=12544, N=128, K=1280 -> 98 CTAs
    mma_gemm<0><<<dim3(M_CONV / 128, 1, 1), 256, GEMM_SMEM_BYTES>>>(
        conv_w, conv_b, CONV_CIN, CONV_COUT, CONV_CIN);

    // 3) dummy keeps fc1 GEMM in ncu's profiled slot (launch #4)
    dummy_kernel<<<1, 32>>>();

    // 4) fc1: M=256, N=4096, K=6272, split-K=2 -> 128 CTAs
    mma_gemm<1><<<dim3(BATCH / 128, N_FC1 / 128, SPLIT1), 256, GEMM_SMEM_BYTES>>>(
        fc1_w, nullptr, K_FC1, N_FC1, K_FC1 / SPLIT1);
    reduce_fc1<<<(BATCH * N_FC1 + 255) / 256, 256>>>(fc1_b);

    // 5) fc2: M=256, N=1470 (12 n-tiles), K=4096, split-K=4 -> 96 CTAs
    mma_gemm<2><<<dim3(BATCH / 128, 12, SPLIT2), 256, GEMM_SMEM_BYTES>>>(
        fc2_w, nullptr, N_FC1, N_FC2, N_FC1 / SPLIT2);
    reduce_fc2<<<(BATCH * N_FC2 + 255) / 256, 256>>>(fc2_b);

    // 6) decode + NMS + top-k
    nms_kernel<<<BATCH, 128>>>(out);
}